// round 15
// baseline (speedup 1.0000x reference)
#include <cuda_runtime.h>

#define B_ 32
#define N_ 524288          // 2^19 points per batch
#define K_ 16384
#define T_RANK 425984u     // 3.25 * 2^17; E[cand] ~ 18.6k, 17 sigma above K
#define CAP 32768          // per-batch candidate capacity (15-bit slot)
#define FBINS 8192         // bins: bin = rank>>6 (only bins < 6656 used)
#define EX_CAP 64          // boundary-bin extras capacity
#define BG_BPB 26          // bingather blocks per batch (26*256 = 6656 bins)
#define SEG_CAP 1280       // max keys per 256-bin segment (E~716, >20 sigma)
#define MBLK_PER_B 512     // producer blocks per batch (1024 elems each)
#define MAIN_BLKS (B_ * MBLK_PER_B)
#define GRID_BLKS (MAIN_BLKS + B_ * BG_BPB)

// key layout: [56:34]=rank(23)  [33:15]=idx(19)  [14:0]=slot(15)

// ---------------- static device scratch (zero-init; kernel restores invariants) ----------------
__device__ int                g_cand_cnt[B_];
__device__ unsigned           g_hist[B_ * FBINS];
__device__ unsigned long long g_cand[B_ * CAP];
__device__ float4             g_cxyz[B_ * CAP];
__device__ unsigned           g_binstart[B_ * FBINS];
__device__ unsigned long long g_dst[B_ * K_];
__device__ unsigned long long g_extras[B_ * EX_CAP];
__device__ int                g_extra_cnt[B_];
__device__ unsigned           g_bstar[B_], g_base[B_], g_need[B_];
__device__ unsigned           g_done[B_];               // producer completion counter
__device__ unsigned           g_ready[B_];              // batch ready flag for consumers
__device__ unsigned           g_bdone[B_];              // consumer completion counter

struct KeysParam { unsigned k[2 * B_]; };

// ---------------- threefry2x32, 20 rounds (exact JAX partitionable) ----------------
__host__ __device__ __forceinline__ unsigned rotl32(unsigned x, int r) {
#if defined(__CUDA_ARCH__)
    return __funnelshift_l(x, x, r);
#else
    return (x << r) | (x >> (32 - r));
#endif
}

__host__ __device__ __forceinline__ void tf2x32(unsigned k0, unsigned k1,
                                                unsigned x0, unsigned x1,
                                                unsigned& o0, unsigned& o1) {
    unsigned ks2 = k0 ^ k1 ^ 0x1BD11BDAu;
    x0 += k0; x1 += k1;
#define TF_ROUND(r) { x0 += x1; x1 = rotl32(x1, r); x1 ^= x0; }
    TF_ROUND(13) TF_ROUND(15) TF_ROUND(26) TF_ROUND(6)
    x0 += k1;  x1 += ks2 + 1u;
    TF_ROUND(17) TF_ROUND(29) TF_ROUND(16) TF_ROUND(24)
    x0 += ks2; x1 += k0 + 2u;
    TF_ROUND(13) TF_ROUND(15) TF_ROUND(26) TF_ROUND(6)
    x0 += k0;  x1 += k1 + 3u;
    TF_ROUND(17) TF_ROUND(29) TF_ROUND(16) TF_ROUND(24)
    x0 += k1;  x1 += ks2 + 4u;
    TF_ROUND(13) TF_ROUND(15) TF_ROUND(26) TF_ROUND(6)
    x0 += ks2; x1 += k0 + 5u;
#undef TF_ROUND
    o0 = x0; o1 = x1;
}

// ---------------- fully fused pipeline kernel ----------------
__global__ void __launch_bounds__(256, 6)
k_all(const float* __restrict__ p, float* __restrict__ out, KeysParam keys) {
    __shared__ char smem_u[32768];                      // union: offs[FBINS] | seg[SEG_CAP]
    __shared__ int s_woff[8];
    __shared__ int s_base;
    __shared__ unsigned s_wsum[8];
    __shared__ int s_ecnt;
    __shared__ unsigned s_bstar;
    __shared__ bool s_last;
    __shared__ unsigned long long sx[EX_CAP];

    int blk = blockIdx.x;
    int t   = threadIdx.x;                              // 256 threads

    if (blk < MAIN_BLKS) {
        // ================= producer: main pass =================
        unsigned b  = (unsigned)(blk >> 9);
        unsigned e0 = (unsigned)blk * 1024u + (unsigned)t * 4u;
        unsigned i0 = e0 & (N_ - 1);

        const float4* pv = reinterpret_cast<const float4*>(p + ((size_t)b * N_ + i0) * 3);
        float4 v0 = pv[0], v1 = pv[1], v2 = pv[2];
        float c[12] = { v0.x, v0.y, v0.z, v0.w, v1.x, v1.y,
                        v1.z, v1.w, v2.x, v2.y, v2.z, v2.w };

        unsigned k0 = keys.k[2 * b], k1 = keys.k[2 * b + 1];

        unsigned rank[4];
        bool cand[4];
#pragma unroll
        for (int j = 0; j < 4; j++) {
            float s = (c[3 * j] + c[3 * j + 1]) + c[3 * j + 2];   // XLA left-assoc sum
            unsigned a, d;
            tf2x32(k0, k1, 0u, i0 + (unsigned)j, a, d);           // counter (0, i)
            rank[j] = (a ^ d) >> 9;
            cand[j] = (s != 0.0f) && (rank[j] < T_RANK);
        }

        unsigned lane = (unsigned)t & 31u;
        unsigned wid  = (unsigned)t >> 5;
        unsigned lt_mask = (1u << lane) - 1u;
        unsigned msk[4];
        int tot = 0;
#pragma unroll
        for (int j = 0; j < 4; j++) {
            msk[j] = __ballot_sync(0xFFFFFFFFu, cand[j]);
            tot += __popc(msk[j]);
        }
        if (lane == 0) s_woff[wid] = tot;
        __syncthreads();
        if (t == 0) {
            int sum = 0;
#pragma unroll
            for (int w = 0; w < 8; w++) { int cc = s_woff[w]; s_woff[w] = sum; sum += cc; }
            s_base = atomicAdd(&g_cand_cnt[b], sum);
        }
        __syncthreads();
        int running = s_base + s_woff[wid];
#pragma unroll
        for (int j = 0; j < 4; j++) {
            if (cand[j]) {
                int pos = running + __popc(msk[j] & lt_mask);
                if (pos < CAP) {
                    size_t sl = (size_t)b * CAP + pos;
                    g_cand[sl] =
                        ((unsigned long long)rank[j] << 34) |
                        ((unsigned long long)(i0 + j) << 15) |
                        (unsigned long long)pos;
                    g_cxyz[sl] = make_float4(c[3 * j], c[3 * j + 1], c[3 * j + 2], 0.0f);
                }
                atomicAdd(&g_hist[b * FBINS + (rank[j] >> 6)], 1u);
            }
            running += __popc(msk[j]);
        }

        // ---- completion; last block of batch runs fused scansc ----
        __threadfence();
        __syncthreads();
        if (t == 0) s_last = (atomicAdd(&g_done[b], 1u) == (unsigned)(MBLK_PER_B - 1));
        __syncthreads();
        if (!s_last) return;
        __threadfence();

        // ================= fused scansc (256 threads) =================
        unsigned* offs = reinterpret_cast<unsigned*>(smem_u);
        unsigned* hist = &g_hist[b * FBINS];
        if (t == 0) s_ecnt = 0;
        {
            const uint4* hv = reinterpret_cast<const uint4*>(hist);
            uint4* hw = reinterpret_cast<uint4*>(hist);
            uint4* ov = reinterpret_cast<uint4*>(offs);
            uint4 z = make_uint4(0, 0, 0, 0);
#pragma unroll
            for (int r = 0; r < 8; r++) {
                int ii = t + 256 * r;
                uint4 v = hv[ii];
                ov[ii] = v;
                hw[ii] = z;                              // zero hist for replay
            }
        }
        __syncthreads();

        unsigned run = 0;
#pragma unroll 4
        for (int r = 0; r < 32; r++) run += offs[t * 32 + r];
        unsigned wincl = run;
        for (int off = 1; off < 32; off <<= 1) {
            unsigned v = __shfl_up_sync(0xFFFFFFFFu, wincl, off);
            if (lane >= (unsigned)off) wincl += v;
        }
        if (lane == 31u) s_wsum[wid] = wincl;
        __syncthreads();
        unsigned wbase = 0;
        for (unsigned w = 0; w < wid; w++) wbase += s_wsum[w];
        unsigned excl = wbase + wincl - run;

        // in-place exclusive offsets + crossing detection + publish binstart
        unsigned pref = excl;
        for (int r = 0; r < 32; r++) {
            unsigned bin = (unsigned)t * 32u + (unsigned)r;
            unsigned cc = offs[bin];
            offs[bin] = pref;
            g_binstart[b * FBINS + bin] = pref;
            if (pref < (unsigned)K_ && pref + cc >= (unsigned)K_) {
                s_bstar    = bin;
                g_bstar[b] = bin;
                g_base[b]  = pref;
                g_need[b]  = (unsigned)K_ - pref;
            }
            pref += cc;
        }
        __syncthreads();

        unsigned bstar = s_bstar;
        const unsigned long long* candp = &g_cand[(size_t)b * CAP];
        unsigned long long* dst = &g_dst[(size_t)b * K_];
        int C = g_cand_cnt[b]; if (C > CAP) C = CAP;

        // scatter, 4-deep prefetch for MLP
        for (int i = t; i < C; i += 1024) {
            unsigned long long kq[4];
#pragma unroll
            for (int q = 0; q < 4; q++)
                if (i + q * 256 < C) kq[q] = candp[i + q * 256];
#pragma unroll
            for (int q = 0; q < 4; q++) {
                if (i + q * 256 < C) {
                    unsigned bin = (unsigned)(kq[q] >> 40);
                    if (bin < bstar) {
                        unsigned pos = atomicAdd(&offs[bin], 1u);
                        dst[pos] = kq[q];
                    } else if (bin == bstar) {
                        int ep = atomicAdd(&s_ecnt, 1);
                        if (ep < EX_CAP) g_extras[b * EX_CAP + ep] = kq[q];
                    }
                }
            }
        }
        __syncthreads();
        if (t == 0) {
            g_extra_cnt[b] = s_ecnt;
            g_cand_cnt[b]  = 0;                          // replay reset
            g_done[b]      = 0;                          // replay reset
            __threadfence();
            atomicExch(&g_ready[b], 1u);                 // release
        }
        return;
    }

    // ================= consumer: bingather =================
    {
        int w = blk - MAIN_BLKS;
        int b = w / BG_BPB;
        int g = w % BG_BPB;
        unsigned bin0 = (unsigned)(g * 256);

        if (t == 0) {
            while (atomicAdd(&g_ready[b], 0u) == 0u) __nanosleep(128);
        }
        __syncthreads();
        __threadfence();                                 // acquire-ish

        unsigned bstar = g_bstar[b];
        float* ob = out + (size_t)b * K_ * 3;
        const unsigned long long* dst = &g_dst[(size_t)b * K_];
        const unsigned* bs = &g_binstart[b * FBINS];
        const float4* cxyz = &g_cxyz[(size_t)b * CAP];
        unsigned long long* seg = reinterpret_cast<unsigned long long*>(smem_u);

        unsigned binEnd = bin0 + 256u; if (binEnd > bstar) binEnd = bstar;
        if (bin0 < bstar) {
            unsigned lo  = bs[bin0];
            unsigned hi  = bs[binEnd];
            unsigned len = hi - lo; if (len > SEG_CAP) len = SEG_CAP;

            for (unsigned i = t; i < len; i += 256) seg[i] = dst[lo + i];
            __syncthreads();

            unsigned bin = bin0 + (unsigned)t;
            if (bin < binEnd) {
                unsigned s = bs[bin] - lo;
                unsigned e = bs[bin + 1] - lo;
                if (e > len) e = len;
                if (s > len) s = len;
                for (unsigned i = s + 1; i < e; i++) {
                    unsigned long long v = seg[i];
                    unsigned jj = i;
                    while (jj > s && seg[jj - 1] > v) { seg[jj] = seg[jj - 1]; jj--; }
                    seg[jj] = v;
                }
            }
            __syncthreads();

            for (unsigned i = t; i < len; i += 256) {
                unsigned slot = (unsigned)(seg[i] & 0x7FFFull);
                unsigned pos = lo + i;
                float4 v = cxyz[slot];
                ob[(size_t)pos * 3 + 0] = v.x;
                ob[(size_t)pos * 3 + 1] = v.y;
                ob[(size_t)pos * 3 + 2] = v.z;
            }
        }

        if (g == BG_BPB - 1 && t < 32) {                 // extras warp
            unsigned lane = (unsigned)t;
            int ec = g_extra_cnt[b]; if (ec > EX_CAP) ec = EX_CAP;
            for (int i = lane; i < EX_CAP; i += 32)
                sx[i] = (i < ec) ? g_extras[b * EX_CAP + i] : 0xFFFFFFFFFFFFFFFFull;
            __syncwarp();
            for (int k = 2; k <= EX_CAP; k <<= 1) {
                for (int j = k >> 1; j > 0; j >>= 1) {
                    unsigned i = ((lane & ~(unsigned)(j - 1)) << 1) | (lane & (unsigned)(j - 1));
                    unsigned ixj = i | (unsigned)j;
                    bool up = ((i & (unsigned)k) == 0);
                    unsigned long long a = sx[i], cc = sx[ixj];
                    if (up ? (a > cc) : (a < cc)) { sx[i] = cc; sx[ixj] = a; }
                    __syncwarp();
                }
            }
            unsigned base = g_base[b], need = g_need[b];
            for (unsigned i = lane; i < need && i < EX_CAP; i += 32) {
                unsigned slot = (unsigned)(sx[i] & 0x7FFFull);
                unsigned pos = base + i;
                float4 v = cxyz[slot];
                ob[(size_t)pos * 3 + 0] = v.x;
                ob[(size_t)pos * 3 + 1] = v.y;
                ob[(size_t)pos * 3 + 2] = v.z;
            }
            if (lane == 0) g_extra_cnt[b] = 0;           // replay reset
        }

        // last consumer of batch resets the ready flag for graph replay
        __threadfence();
        __syncthreads();
        if (t == 0) {
            if (atomicAdd(&g_bdone[b], 1u) == (unsigned)(BG_BPB - 1)) {
                g_bdone[b] = 0;
                atomicExch(&g_ready[b], 0u);
            }
        }
    }
}

// ---------------- launch: single fused kernel ----------------
extern "C" void kernel_launch(void* const* d_in, const int* in_sizes, int n_in,
                              void* d_out, int out_size) {
    const float* p = (const float*)d_in[0];
    float* out = (float*)d_out;

    KeysParam kp;
    for (int b = 0; b < B_; b++) {
        unsigned kb0, kb1, s0, s1;
        tf2x32(0u, 42u, 0u, (unsigned)b, kb0, kb1);
        tf2x32(kb0, kb1, 0u, 0u, s0, s1);
        kp.k[2 * b]     = s0;
        kp.k[2 * b + 1] = s1;
    }

    k_all<<<GRID_BLKS, 256>>>(p, out, kp);
}

// round 16
// speedup vs baseline: 1.0313x; 1.0313x over previous
#include <cuda_runtime.h>

#define B_ 32
#define N_ 524288          // 2^19 points per batch
#define K_ 16384
#define T_RANK 425984u     // 3.25 * 2^17; E[cand] ~ 18.6k, 17 sigma above K
#define CAP 32768          // per-batch candidate capacity (15-bit slot)
#define FBINS 8192         // bins: bin = rank>>6 (only bins < 6656 used)
#define EX_CAP 64          // boundary-bin extras capacity
#define BG_BPB 26          // bingather blocks per batch (26*256 = 6656 bins)
#define SEG_CAP 1280       // max keys per 256-bin segment (E~716, >20 sigma)
#define MBLK_PER_B 512     // producer blocks per batch (1024 elems each)
#define MAIN_BLKS (B_ * MBLK_PER_B)

// key layout: [56:34]=rank(23)  [33:15]=idx(19)  [14:0]=slot(15)

// ---------------- static device scratch (zero-init; kernels restore invariants) ----------------
__device__ int                g_cand_cnt[B_];
__device__ unsigned           g_hist[B_ * FBINS];
__device__ unsigned long long g_cand[B_ * CAP];
__device__ float4             g_cxyz[B_ * CAP];
__device__ unsigned           g_binstart[B_ * FBINS];
__device__ unsigned long long g_dst[B_ * K_];
__device__ unsigned long long g_extras[B_ * EX_CAP];
__device__ int                g_extra_cnt[B_];
__device__ unsigned           g_bstar[B_], g_base[B_], g_need[B_];
__device__ unsigned           g_done[B_];               // producer completion counter

struct KeysParam { unsigned k[2 * B_]; };

// ---------------- threefry2x32, 20 rounds (exact JAX partitionable) ----------------
__host__ __device__ __forceinline__ unsigned rotl32(unsigned x, int r) {
#if defined(__CUDA_ARCH__)
    return __funnelshift_l(x, x, r);
#else
    return (x << r) | (x >> (32 - r));
#endif
}

__host__ __device__ __forceinline__ void tf2x32(unsigned k0, unsigned k1,
                                                unsigned x0, unsigned x1,
                                                unsigned& o0, unsigned& o1) {
    unsigned ks2 = k0 ^ k1 ^ 0x1BD11BDAu;
    x0 += k0; x1 += k1;
#define TF_ROUND(r) { x0 += x1; x1 = rotl32(x1, r); x1 ^= x0; }
    TF_ROUND(13) TF_ROUND(15) TF_ROUND(26) TF_ROUND(6)
    x0 += k1;  x1 += ks2 + 1u;
    TF_ROUND(17) TF_ROUND(29) TF_ROUND(16) TF_ROUND(24)
    x0 += ks2; x1 += k0 + 2u;
    TF_ROUND(13) TF_ROUND(15) TF_ROUND(26) TF_ROUND(6)
    x0 += k0;  x1 += k1 + 3u;
    TF_ROUND(17) TF_ROUND(29) TF_ROUND(16) TF_ROUND(24)
    x0 += k1;  x1 += ks2 + 4u;
    TF_ROUND(13) TF_ROUND(15) TF_ROUND(26) TF_ROUND(6)
    x0 += ks2; x1 += k0 + 5u;
#undef TF_ROUND
    o0 = x0; o1 = x1;
}

// ---------------- P1: main pass + last-block-per-batch fused scansc ----------------
__global__ void __launch_bounds__(256)
k_mainsc(const float* __restrict__ p, KeysParam keys) {
    __shared__ unsigned offs[FBINS];                     // 32 KB (scansc phase only)
    __shared__ int s_woff[8];
    __shared__ int s_base;
    __shared__ unsigned s_wsum[8];
    __shared__ int s_ecnt;
    __shared__ unsigned s_bstar;
    __shared__ bool s_last;

    int blk = blockIdx.x;
    int t   = threadIdx.x;                               // 256 threads
    unsigned b  = (unsigned)(blk >> 9);
    unsigned e0 = (unsigned)blk * 1024u + (unsigned)t * 4u;
    unsigned i0 = e0 & (N_ - 1);

    const float4* pv = reinterpret_cast<const float4*>(p + ((size_t)b * N_ + i0) * 3);
    float4 v0 = pv[0], v1 = pv[1], v2 = pv[2];
    float c[12] = { v0.x, v0.y, v0.z, v0.w, v1.x, v1.y,
                    v1.z, v1.w, v2.x, v2.y, v2.z, v2.w };

    unsigned k0 = keys.k[2 * b], k1 = keys.k[2 * b + 1];

    unsigned rank[4];
    bool cand[4];
#pragma unroll
    for (int j = 0; j < 4; j++) {
        float s = (c[3 * j] + c[3 * j + 1]) + c[3 * j + 2];   // XLA left-assoc sum
        unsigned a, d;
        tf2x32(k0, k1, 0u, i0 + (unsigned)j, a, d);           // counter (0, i)
        rank[j] = (a ^ d) >> 9;
        cand[j] = (s != 0.0f) && (rank[j] < T_RANK);
    }

    unsigned lane = (unsigned)t & 31u;
    unsigned wid  = (unsigned)t >> 5;
    unsigned lt_mask = (1u << lane) - 1u;
    unsigned msk[4];
    int tot = 0;
#pragma unroll
    for (int j = 0; j < 4; j++) {
        msk[j] = __ballot_sync(0xFFFFFFFFu, cand[j]);
        tot += __popc(msk[j]);
    }
    if (lane == 0) s_woff[wid] = tot;
    __syncthreads();
    if (t == 0) {
        int sum = 0;
#pragma unroll
        for (int w = 0; w < 8; w++) { int cc = s_woff[w]; s_woff[w] = sum; sum += cc; }
        s_base = atomicAdd(&g_cand_cnt[b], sum);
    }
    __syncthreads();
    int running = s_base + s_woff[wid];
#pragma unroll
    for (int j = 0; j < 4; j++) {
        if (cand[j]) {
            int pos = running + __popc(msk[j] & lt_mask);
            if (pos < CAP) {
                size_t sl = (size_t)b * CAP + pos;
                g_cand[sl] =
                    ((unsigned long long)rank[j] << 34) |
                    ((unsigned long long)(i0 + j) << 15) |
                    (unsigned long long)pos;
                g_cxyz[sl] = make_float4(c[3 * j], c[3 * j + 1], c[3 * j + 2], 0.0f);
            }
            atomicAdd(&g_hist[b * FBINS + (rank[j] >> 6)], 1u);
        }
        running += __popc(msk[j]);
    }

    // ---- completion; last block of batch runs fused scansc ----
    __threadfence();
    __syncthreads();
    if (t == 0) s_last = (atomicAdd(&g_done[b], 1u) == (unsigned)(MBLK_PER_B - 1));
    __syncthreads();
    if (!s_last) return;
    __threadfence();

    // ================= fused scansc (256 threads; verified in R15) =================
    unsigned* hist = &g_hist[b * FBINS];
    if (t == 0) s_ecnt = 0;
    {
        const uint4* hv = reinterpret_cast<const uint4*>(hist);
        uint4* hw = reinterpret_cast<uint4*>(hist);
        uint4* ov = reinterpret_cast<uint4*>(offs);
        uint4 z = make_uint4(0, 0, 0, 0);
#pragma unroll
        for (int r = 0; r < 8; r++) {
            int ii = t + 256 * r;
            uint4 v = hv[ii];
            ov[ii] = v;
            hw[ii] = z;                                  // zero hist for replay
        }
    }
    __syncthreads();

    unsigned run = 0;
#pragma unroll 4
    for (int r = 0; r < 32; r++) run += offs[t * 32 + r];
    unsigned wincl = run;
    for (int off = 1; off < 32; off <<= 1) {
        unsigned v = __shfl_up_sync(0xFFFFFFFFu, wincl, off);
        if (lane >= (unsigned)off) wincl += v;
    }
    if (lane == 31u) s_wsum[wid] = wincl;
    __syncthreads();
    unsigned wbase = 0;
    for (unsigned w = 0; w < wid; w++) wbase += s_wsum[w];
    unsigned excl = wbase + wincl - run;

    unsigned pref = excl;
    for (int r = 0; r < 32; r++) {
        unsigned bin = (unsigned)t * 32u + (unsigned)r;
        unsigned cc = offs[bin];
        offs[bin] = pref;
        g_binstart[b * FBINS + bin] = pref;
        if (pref < (unsigned)K_ && pref + cc >= (unsigned)K_) {
            s_bstar    = bin;
            g_bstar[b] = bin;
            g_base[b]  = pref;
            g_need[b]  = (unsigned)K_ - pref;
        }
        pref += cc;
    }
    __syncthreads();

    unsigned bstar = s_bstar;
    const unsigned long long* candp = &g_cand[(size_t)b * CAP];
    unsigned long long* dst = &g_dst[(size_t)b * K_];
    int C = g_cand_cnt[b]; if (C > CAP) C = CAP;

    // scatter, 4-deep prefetch for MLP
    for (int i = t; i < C; i += 1024) {
        unsigned long long kq[4];
#pragma unroll
        for (int q = 0; q < 4; q++)
            if (i + q * 256 < C) kq[q] = candp[i + q * 256];
#pragma unroll
        for (int q = 0; q < 4; q++) {
            if (i + q * 256 < C) {
                unsigned bin = (unsigned)(kq[q] >> 40);
                if (bin < bstar) {
                    unsigned pos = atomicAdd(&offs[bin], 1u);
                    dst[pos] = kq[q];
                } else if (bin == bstar) {
                    int ep = atomicAdd(&s_ecnt, 1);
                    if (ep < EX_CAP) g_extras[b * EX_CAP + ep] = kq[q];
                }
            }
        }
    }
    __syncthreads();
    if (t == 0) {
        g_extra_cnt[b] = s_ecnt;
        g_cand_cnt[b]  = 0;                              // replay reset
        g_done[b]      = 0;                              // replay reset
    }
}

// ---------------- P2: segment-staged per-bin sort + L2-resident float4 gather ----------------
__global__ void k_bingather(float* __restrict__ out) {
    __shared__ unsigned long long seg[SEG_CAP];
    __shared__ unsigned long long sx[EX_CAP];

    int blk = blockIdx.x;
    int b   = blk / BG_BPB;
    int g   = blk % BG_BPB;
    int t   = threadIdx.x;                               // 256 threads
    unsigned bin0  = (unsigned)(g * 256);
    unsigned bstar = g_bstar[b];

    float* ob = out + (size_t)b * K_ * 3;
    const unsigned long long* dst = &g_dst[(size_t)b * K_];
    const unsigned* bs = &g_binstart[b * FBINS];
    const float4* cxyz = &g_cxyz[(size_t)b * CAP];

    unsigned binEnd = bin0 + 256u; if (binEnd > bstar) binEnd = bstar;
    if (bin0 < bstar) {
        unsigned lo  = bs[bin0];
        unsigned hi  = bs[binEnd];
        unsigned len = hi - lo; if (len > SEG_CAP) len = SEG_CAP;

        for (unsigned i = t; i < len; i += 256) seg[i] = dst[lo + i];
        __syncthreads();

        unsigned bin = bin0 + (unsigned)t;
        if (bin < binEnd) {
            unsigned s = bs[bin] - lo;
            unsigned e = bs[bin + 1] - lo;
            if (e > len) e = len;
            if (s > len) s = len;
            for (unsigned i = s + 1; i < e; i++) {
                unsigned long long v = seg[i];
                unsigned jj = i;
                while (jj > s && seg[jj - 1] > v) { seg[jj] = seg[jj - 1]; jj--; }
                seg[jj] = v;
            }
        }
        __syncthreads();

        for (unsigned i = t; i < len; i += 256) {
            unsigned slot = (unsigned)(seg[i] & 0x7FFFull);
            unsigned pos = lo + i;
            float4 v = cxyz[slot];
            ob[(size_t)pos * 3 + 0] = v.x;
            ob[(size_t)pos * 3 + 1] = v.y;
            ob[(size_t)pos * 3 + 2] = v.z;
        }
    }

    if (g == BG_BPB - 1 && t < 32) {                     // extras warp
        unsigned lane = (unsigned)t;
        int ec = g_extra_cnt[b]; if (ec > EX_CAP) ec = EX_CAP;
        for (int i = lane; i < EX_CAP; i += 32)
            sx[i] = (i < ec) ? g_extras[b * EX_CAP + i] : 0xFFFFFFFFFFFFFFFFull;
        __syncwarp();
        for (int k = 2; k <= EX_CAP; k <<= 1) {
            for (int j = k >> 1; j > 0; j >>= 1) {
                unsigned i = ((lane & ~(unsigned)(j - 1)) << 1) | (lane & (unsigned)(j - 1));
                unsigned ixj = i | (unsigned)j;
                bool up = ((i & (unsigned)k) == 0);
                unsigned long long a = sx[i], cc = sx[ixj];
                if (up ? (a > cc) : (a < cc)) { sx[i] = cc; sx[ixj] = a; }
                __syncwarp();
            }
        }
        unsigned base = g_base[b], need = g_need[b];
        for (unsigned i = lane; i < need && i < EX_CAP; i += 32) {
            unsigned slot = (unsigned)(sx[i] & 0x7FFFull);
            unsigned pos = base + i;
            float4 v = cxyz[slot];
            ob[(size_t)pos * 3 + 0] = v.x;
            ob[(size_t)pos * 3 + 1] = v.y;
            ob[(size_t)pos * 3 + 2] = v.z;
        }
        if (lane == 0) g_extra_cnt[b] = 0;               // replay reset
    }
}

// ---------------- launch ----------------
extern "C" void kernel_launch(void* const* d_in, const int* in_sizes, int n_in,
                              void* d_out, int out_size) {
    const float* p = (const float*)d_in[0];
    float* out = (float*)d_out;

    KeysParam kp;
    for (int b = 0; b < B_; b++) {
        unsigned kb0, kb1, s0, s1;
        tf2x32(0u, 42u, 0u, (unsigned)b, kb0, kb1);
        tf2x32(kb0, kb1, 0u, 0u, s0, s1);
        kp.k[2 * b]     = s0;
        kp.k[2 * b + 1] = s1;
    }

    k_mainsc<<<MAIN_BLKS, 256>>>(p, kp);
    k_bingather<<<B_ * BG_BPB, 256>>>(out);
}

// round 17
// speedup vs baseline: 1.6063x; 1.5575x over previous
#include <cuda_runtime.h>

#define B_ 32
#define N_ 524288          // 2^19 points per batch
#define K_ 16384
#define T_RANK 425984u     // 3.25 * 2^17; E[cand] ~ 18.6k, 17 sigma above K
#define CAP 32768          // per-batch candidate capacity (15-bit slot)
#define FBINS 8192         // bins: bin = rank>>6 (only bins < 6656 used)
#define EX_CAP 64          // boundary-bin extras capacity
#define BG_BPB 26          // tail blocks per batch (26*256 = 6656 bins)
#define SEGMAX 4096        // seg smem capacity in keys (32 KB / 8B)

// key layout: [56:34]=rank(23)  [33:15]=idx(19)  [14:0]=slot(15)
// bin = key>>40 = rank>>6. Sorting by key == sorting by (rank, idx).

// ---------------- static device scratch (zero-init; kernels restore invariants) ----------------
__device__ int                g_cand_cnt[B_];
__device__ unsigned           g_hist[B_ * FBINS];      // built by k_main, zeroed by k_tail
__device__ unsigned long long g_cand[B_ * CAP];        // unordered candidate keys
__device__ float4             g_cxyz[B_ * CAP];        // candidate coords (L2-resident)
__device__ unsigned           g_bdone[B_];             // tail completion counter

struct KeysParam { unsigned k[2 * B_]; };

// ---------------- threefry2x32, 20 rounds (exact JAX partitionable) ----------------
__host__ __device__ __forceinline__ unsigned rotl32(unsigned x, int r) {
#if defined(__CUDA_ARCH__)
    return __funnelshift_l(x, x, r);
#else
    return (x << r) | (x >> (32 - r));
#endif
}

__host__ __device__ __forceinline__ void tf2x32(unsigned k0, unsigned k1,
                                                unsigned x0, unsigned x1,
                                                unsigned& o0, unsigned& o1) {
    unsigned ks2 = k0 ^ k1 ^ 0x1BD11BDAu;
    x0 += k0; x1 += k1;
#define TF_ROUND(r) { x0 += x1; x1 = rotl32(x1, r); x1 ^= x0; }
    TF_ROUND(13) TF_ROUND(15) TF_ROUND(26) TF_ROUND(6)
    x0 += k1;  x1 += ks2 + 1u;
    TF_ROUND(17) TF_ROUND(29) TF_ROUND(16) TF_ROUND(24)
    x0 += ks2; x1 += k0 + 2u;
    TF_ROUND(13) TF_ROUND(15) TF_ROUND(26) TF_ROUND(6)
    x0 += k0;  x1 += k1 + 3u;
    TF_ROUND(17) TF_ROUND(29) TF_ROUND(16) TF_ROUND(24)
    x0 += k1;  x1 += ks2 + 4u;
    TF_ROUND(13) TF_ROUND(15) TF_ROUND(26) TF_ROUND(6)
    x0 += ks2; x1 += k0 + 5u;
#undef TF_ROUND
    o0 = x0; o1 = x1;
}

// ---------------- P1: validity + threefry + collect + histogram (pristine R12 form) ----------------
__global__ void k_main(const float* __restrict__ p, KeysParam keys) {
    __shared__ int s_woff[8];
    __shared__ int s_base;

    unsigned t  = blockIdx.x * blockDim.x + threadIdx.x;   // one thread = 4 points
    unsigned e0 = t * 4u;
    unsigned b  = e0 >> 19;
    unsigned i0 = e0 & (N_ - 1);

    const float4* pv = reinterpret_cast<const float4*>(p) + (size_t)t * 3;
    float4 v0 = pv[0], v1 = pv[1], v2 = pv[2];
    float c[12] = { v0.x, v0.y, v0.z, v0.w, v1.x, v1.y,
                    v1.z, v1.w, v2.x, v2.y, v2.z, v2.w };

    unsigned k0 = keys.k[2 * b], k1 = keys.k[2 * b + 1];

    unsigned rank[4];
    bool cand[4];
#pragma unroll
    for (int j = 0; j < 4; j++) {
        float s = (c[3 * j] + c[3 * j + 1]) + c[3 * j + 2];   // XLA left-assoc sum
        unsigned a, d;
        tf2x32(k0, k1, 0u, i0 + (unsigned)j, a, d);           // counter (0, i)
        rank[j] = (a ^ d) >> 9;                               // 23-bit rank
        cand[j] = (s != 0.0f) && (rank[j] < T_RANK);
    }

    unsigned lane = threadIdx.x & 31u;
    unsigned wid  = threadIdx.x >> 5;
    unsigned lt_mask = (1u << lane) - 1u;
    unsigned msk[4];
    int tot = 0;
#pragma unroll
    for (int j = 0; j < 4; j++) {
        msk[j] = __ballot_sync(0xFFFFFFFFu, cand[j]);
        tot += __popc(msk[j]);
    }
    if (lane == 0) s_woff[wid] = tot;
    __syncthreads();
    if (threadIdx.x == 0) {
        int sum = 0;
#pragma unroll
        for (int w = 0; w < 8; w++) { int cc = s_woff[w]; s_woff[w] = sum; sum += cc; }
        s_base = atomicAdd(&g_cand_cnt[b], sum);
    }
    __syncthreads();
    int running = s_base + s_woff[wid];
#pragma unroll
    for (int j = 0; j < 4; j++) {
        if (cand[j]) {
            int pos = running + __popc(msk[j] & lt_mask);
            if (pos < CAP) {
                size_t sl = (size_t)b * CAP + pos;
                g_cand[sl] =
                    ((unsigned long long)rank[j] << 34) |
                    ((unsigned long long)(i0 + j) << 15) |
                    (unsigned long long)pos;
                g_cxyz[sl] = make_float4(c[3 * j], c[3 * j + 1], c[3 * j + 2], 0.0f);
            }
            atomicAdd(&g_hist[b * FBINS + (rank[j] >> 6)], 1u);   // RED, no return
        }
        running += __popc(msk[j]);
    }
}

// ---------------- P2: independent tail blocks — redundant scan + filter + sort + gather ----------------
__global__ void k_tail(float* __restrict__ out) {
    __shared__ __align__(16) unsigned hstage[FBINS];     // 32 KB; reused as seg (ull) after scan
    __shared__ unsigned s_off[257];                      // binstart for bins [bin0, bin0+256]
    __shared__ unsigned woff[256];                       // scatter working offsets (relative)
    __shared__ unsigned s_wsum[8];
    __shared__ unsigned s_bstar, s_base, s_need;
    __shared__ int s_ecnt;
    __shared__ unsigned long long sx[EX_CAP];

    int blk = blockIdx.x;
    int b   = blk / BG_BPB;
    int g   = blk % BG_BPB;
    int t   = threadIdx.x;                               // 256 threads
    unsigned lane = (unsigned)t & 31u;
    unsigned wid  = (unsigned)t >> 5;
    unsigned bin0 = (unsigned)(g * 256);

    // ---- stage hist (coalesced; shared across 26 blocks via L2) ----
    const uint4* hv = reinterpret_cast<const uint4*>(&g_hist[b * FBINS]);
    uint4* hs = reinterpret_cast<uint4*>(hstage);
#pragma unroll
    for (int r = 0; r < 8; r++) hs[t + 256 * r] = hv[t + 256 * r];
    if (t == 0) { s_ecnt = 0; s_bstar = 0u; }
    __syncthreads();

    // ---- full scan (32 bins/thread) ----
    unsigned run = 0;
#pragma unroll 4
    for (int r = 0; r < 32; r++) run += hstage[t * 32 + r];
    unsigned wincl = run;
    for (int off = 1; off < 32; off <<= 1) {
        unsigned v = __shfl_up_sync(0xFFFFFFFFu, wincl, off);
        if (lane >= (unsigned)off) wincl += v;
    }
    if (lane == 31u) s_wsum[wid] = wincl;
    __syncthreads();
    unsigned wbase = 0;
    for (unsigned w = 0; w < wid; w++) wbase += s_wsum[w];
    unsigned excl = wbase + wincl - run;

    // walk: record binstart for our range; detect K-crossing
    unsigned pref = excl;
    for (int r = 0; r < 32; r++) {
        unsigned bin = (unsigned)t * 32u + (unsigned)r;
        unsigned cc = hstage[bin];
        if (bin - bin0 <= 256u) s_off[bin - bin0] = pref;     // unsigned wrap excludes bin<bin0
        if (pref < (unsigned)K_ && pref + cc >= (unsigned)K_) {
            s_bstar = bin; s_base = pref; s_need = (unsigned)K_ - pref;
        }
        pref += cc;
    }
    __syncthreads();

    unsigned bstar = s_bstar;
    unsigned binEnd = bin0 + 256u; if (binEnd > bstar) binEnd = bstar;
    bool has_extras = (bstar >= bin0) && (bstar < bin0 + 256u);

    if (bin0 < bstar || has_extras) {
        unsigned lo = s_off[0];
        woff[t] = (bin0 + (unsigned)t < binEnd) ? (s_off[t] - lo) : 0u;
        __syncthreads();                                 // hstage count-reads done -> reuse as seg

        unsigned long long* seg = reinterpret_cast<unsigned long long*>(hstage);
        const unsigned long long* cand = &g_cand[(size_t)b * CAP];
        int C = g_cand_cnt[b]; if (C > CAP) C = CAP;

        // filter + smem scatter
        for (int i = t; i < C; i += 256) {
            unsigned long long key = cand[i];
            unsigned bin = (unsigned)(key >> 40);
            if (bin - bin0 < binEnd - bin0) {            // bin in [bin0, binEnd)
                unsigned pos = atomicAdd(&woff[bin - bin0], 1u);
                if (pos < (unsigned)SEGMAX) seg[pos] = key;
            } else if (has_extras && bin == bstar) {
                int ep = atomicAdd(&s_ecnt, 1);
                if (ep < EX_CAP) sx[ep] = key;
            }
        }
        __syncthreads();

        // per-bin insertion sort in smem (one thread per bin)
        unsigned bin = bin0 + (unsigned)t;
        if (bin < binEnd) {
            unsigned s = s_off[t] - lo;
            unsigned e = s_off[t + 1] - lo;
            if (e > (unsigned)SEGMAX) e = (unsigned)SEGMAX;
            for (unsigned i = s + 1; i < e; i++) {
                unsigned long long v = seg[i];
                unsigned jj = i;
                while (jj > s && seg[jj - 1] > v) { seg[jj] = seg[jj - 1]; jj--; }
                seg[jj] = v;
            }
        }
        // extras warp-bitonic (warp 0) if we own the boundary bin
        if (has_extras && t < 32) {
            int ec = s_ecnt; if (ec > EX_CAP) ec = EX_CAP;
            for (int i = lane; i < EX_CAP; i += 32)
                if (i >= ec) sx[i] = 0xFFFFFFFFFFFFFFFFull;
            __syncwarp();
            for (int k = 2; k <= EX_CAP; k <<= 1) {
                for (int j = k >> 1; j > 0; j >>= 1) {
                    unsigned i = ((lane & ~(unsigned)(j - 1)) << 1) | (lane & (unsigned)(j - 1));
                    unsigned ixj = i | (unsigned)j;
                    bool up = ((i & (unsigned)k) == 0);
                    unsigned long long a = sx[i], cc = sx[ixj];
                    if (up ? (a > cc) : (a < cc)) { sx[i] = cc; sx[ixj] = a; }
                    __syncwarp();
                }
            }
        }
        __syncthreads();

        // gather + write (L2-resident cxyz by slot)
        const float4* cxyz = &g_cxyz[(size_t)b * CAP];
        float* ob = out + (size_t)b * K_ * 3;
        unsigned len = (binEnd > bin0) ? (s_off[binEnd - bin0] - lo) : 0u;
        if (len > (unsigned)SEGMAX) len = (unsigned)SEGMAX;
        for (unsigned i = t; i < len; i += 256) {
            unsigned slot = (unsigned)(seg[i] & 0x7FFFull);
            unsigned pos = lo + i;
            float4 v = cxyz[slot];
            ob[(size_t)pos * 3 + 0] = v.x;
            ob[(size_t)pos * 3 + 1] = v.y;
            ob[(size_t)pos * 3 + 2] = v.z;
        }
        if (has_extras) {
            unsigned base = s_base, need = s_need;
            for (unsigned i = t; i < need && i < (unsigned)EX_CAP; i += 256) {
                unsigned slot = (unsigned)(sx[i] & 0x7FFFull);
                unsigned pos = base + i;
                float4 v = cxyz[slot];
                ob[(size_t)pos * 3 + 0] = v.x;
                ob[(size_t)pos * 3 + 1] = v.y;
                ob[(size_t)pos * 3 + 2] = v.z;
            }
        }
    }

    // ---- replay reset: last tail block of batch zeros hist + counters ----
    __syncthreads();
    if (t == 0) {
        __threadfence();                                 // cheap here: 32 blocks total reach this late
        if (atomicAdd(&g_bdone[b], 1u) == (unsigned)(BG_BPB - 1)) {
            g_bdone[b] = 0;
            g_cand_cnt[b] = 0;
        }
    }
    // last block also zeros the hist region (all reads of it are complete)
    __syncthreads();
    if (atomicAdd(&g_bdone[b], 0u) == 0u && t < 256) {
        // note: only true for the block that just reset the counter in this replay
    }
    // simpler deterministic approach: block g==0..? -> do explicit zero below
    if (g == BG_BPB - 1) {
        // this block zeroes hist AFTER its own reads; other blocks' reads raced ahead of us
        // only safe via the bdone gate above; so spin-free fallback: zero own 1/26 slice is unsafe.
        // Instead: hist zeroing is done by the block that won the bdone gate:
    }
    if (t == 0) { /* no-op */ }
    // Deterministic hist zero: the gate winner zeroes. Re-derive winner via flag in smem.
    __shared__ int s_winner;
    if (t == 0) s_winner = (g_bdone[b] == 0u && g_cand_cnt[b] == 0) ? 0 : 0;
    __syncthreads();
    // The gate winner path: re-check inside t==0 branch above is racy for other blocks;
    // to keep it simple and correct, the winner (which set g_bdone[b]=0) zeroes hist here:
    // We detect winner by having stored it in s_winner at the moment of winning.
    // (set below in the t==0 gate — see s_iswin)
}

// The reset logic above got convoluted; use a clean second pass kernel-side instead:
__global__ void k_reset() {
    // 32 blocks x 256 threads: zero hist for all batches (runs next replay's prologue cheaply)
    int b = blockIdx.x;
    uint4* hw = reinterpret_cast<uint4*>(&g_hist[b * FBINS]);
    uint4 z = make_uint4(0, 0, 0, 0);
#pragma unroll
    for (int r = 0; r < 8; r++) hw[threadIdx.x + 256 * r] = z;
    if (threadIdx.x == 0) { g_cand_cnt[b] = 0; g_bdone[b] = 0; }
}

// ---------------- launch ----------------
extern "C" void kernel_launch(void* const* d_in, const int* in_sizes, int n_in,
                              void* d_out, int out_size) {
    const float* p = (const float*)d_in[0];
    float* out = (float*)d_out;

    KeysParam kp;
    for (int b = 0; b < B_; b++) {
        unsigned kb0, kb1, s0, s1;
        tf2x32(0u, 42u, 0u, (unsigned)b, kb0, kb1);
        tf2x32(kb0, kb1, 0u, 0u, s0, s1);
        kp.k[2 * b]     = s0;
        kp.k[2 * b + 1] = s1;
    }

    k_main<<<(B_ * N_ / 4) / 256, 256>>>(p, kp);
    k_tail<<<B_ * BG_BPB, 256>>>(out);
    k_reset<<<B_, 256>>>();   // tiny (~2 us, overlaps harness epilogue); restores zero-invariants
}